// round 1
// baseline (speedup 1.0000x reference)
#include <cuda_runtime.h>
#include <math.h>

// ---------------------------------------------------------------------------
// APPNP Link prediction.  N=50000 nodes, E=800000 edges, P=200000 pairs,
// D=128 features, K=10 propagation steps x 2 phases, alpha=0.1.
//
// Pipeline per launch (all graph-capturable, no allocations):
//   1. build CSR of A_hat (dst-major, with self loops) + sym-norm values
//   2. h = x @ W1^T + b1            (also saved as x0)
//   3. 10x: h = 0.9 * (A_hat h) + 0.1 * x0
//   4. h = relu(h) @ W2^T + b2      (also saved as x0)
//   5. 10x: h = 0.9 * (A_hat h) + 0.1 * x0
//   6. link head: log_softmax( [relu(h[i]);relu(h[j])] @ W3^T + b3 )
// ---------------------------------------------------------------------------

#define D 128
#define NMAX 50176
#define EMAX 800000
#define CSRMAX (EMAX + NMAX)
#define ALPHA 0.1f

__device__ float g_h [NMAX * D];
__device__ float g_h2[NMAX * D];
__device__ float g_x0[NMAX * D];
__device__ int   g_deg[NMAX];
__device__ float g_dinv[NMAX];
__device__ int   g_rowptr[NMAX + 1];
__device__ int   g_cursor[NMAX];
__device__ int   g_col[CSRMAX];
__device__ float g_val[CSRMAX];
__device__ int   g_bsums[64];

// ---------------------------------------------------------------- CSR build
__global__ void k_init(int n) {
    int i = blockIdx.x * blockDim.x + threadIdx.x;
    if (i < n) { g_deg[i] = 1; g_cursor[i] = 0; }   // 1 = self loop
}

__global__ void k_hist(const int* __restrict__ dst, int e) {
    int i = blockIdx.x * blockDim.x + threadIdx.x;
    if (i < e) atomicAdd(&g_deg[dst[i]], 1);
}

// inclusive scan of g_deg into g_rowptr[i+1]; per-block totals into g_bsums
__global__ void k_scanA(int n) {
    __shared__ int s[1024];
    int gid = blockIdx.x * 1024 + threadIdx.x;
    int v = (gid < n) ? g_deg[gid] : 0;
    s[threadIdx.x] = v;
    __syncthreads();
    for (int off = 1; off < 1024; off <<= 1) {
        int t = (threadIdx.x >= off) ? s[threadIdx.x - off] : 0;
        __syncthreads();
        s[threadIdx.x] += t;
        __syncthreads();
    }
    if (gid < n) g_rowptr[gid + 1] = s[threadIdx.x];
    if (threadIdx.x == 1023) g_bsums[blockIdx.x] = s[1023];
}

__global__ void k_scanB(int nb) {
    __shared__ int s[64];
    int v = (threadIdx.x < nb) ? g_bsums[threadIdx.x] : 0;
    s[threadIdx.x] = v;
    __syncthreads();
    for (int off = 1; off < 64; off <<= 1) {
        int t = (threadIdx.x >= off) ? s[threadIdx.x - off] : 0;
        __syncthreads();
        s[threadIdx.x] += t;
        __syncthreads();
    }
    if (threadIdx.x < nb) g_bsums[threadIdx.x] = s[threadIdx.x] - v;  // exclusive
}

__global__ void k_scanC(int n) {
    int gid = blockIdx.x * 1024 + threadIdx.x;
    if (gid < n) g_rowptr[gid + 1] += g_bsums[blockIdx.x];
    if (gid == 0) g_rowptr[0] = 0;
}

__global__ void k_dinv(int n) {
    int i = blockIdx.x * blockDim.x + threadIdx.x;
    if (i < n) g_dinv[i] = rsqrtf((float)g_deg[i]);
}

__global__ void k_fill(const int* __restrict__ src, const int* __restrict__ dst,
                       int e, int n) {
    int i = blockIdx.x * blockDim.x + threadIdx.x;
    if (i < e) {
        int s = src[i], d = dst[i];
        int pos = g_rowptr[d] + atomicAdd(&g_cursor[d], 1);
        g_col[pos] = s;
        g_val[pos] = g_dinv[s] * g_dinv[d];
    } else if (i < e + n) {
        int nd = i - e;
        int pos = g_rowptr[nd] + atomicAdd(&g_cursor[nd], 1);
        g_col[pos] = nd;
        float dv = g_dinv[nd];
        g_val[pos] = dv * dv;
    }
}

// ---------------------------------------------------------------- dense GEMM
// out[row][f] = sum_k in[row][k] * W[f][k] + bias[f]
// mode 0: in = Xext (no relu), out -> g_h  and g_x0
// mode 1: in = g_h  (relu),    out -> g_h2 and g_x0
__global__ void k_gemm(const float* __restrict__ Xext, const float* __restrict__ W,
                       const float* __restrict__ bias, int mode, int nrows) {
    __shared__ float Wt[64 * 129];                 // Wt[kk][f], padded
    __shared__ __align__(16) float xs[16 * 64];    // xs[r][kk]
    const float* X = (mode == 0) ? Xext : g_h;
    float* out = (mode == 0) ? g_h : g_h2;

    int f = threadIdx.x;           // 0..127, output column
    int row0 = blockIdx.x * 16;
    float acc[16];
#pragma unroll
    for (int r = 0; r < 16; r++) acc[r] = 0.f;

    for (int kc = 0; kc < 128; kc += 64) {
        // load W chunk transposed: coalesced gmem reads, pad-129 smem writes
        for (int i = f; i < 64 * 128; i += 128) {
            int kk = i & 63, f2 = i >> 6;
            Wt[kk * 129 + f2] = W[f2 * 128 + kc + kk];
        }
        // load x tile
        for (int i = f; i < 16 * 64; i += 128) {
            int r = i >> 6, kk = i & 63;
            int row = row0 + r;
            float v = (row < nrows) ? X[row * 128 + kc + kk] : 0.f;
            if (mode) v = fmaxf(v, 0.f);
            xs[i] = v;
        }
        __syncthreads();
#pragma unroll
        for (int kk = 0; kk < 64; kk += 4) {
            float w0 = Wt[(kk + 0) * 129 + f];
            float w1 = Wt[(kk + 1) * 129 + f];
            float w2 = Wt[(kk + 2) * 129 + f];
            float w3 = Wt[(kk + 3) * 129 + f];
#pragma unroll
            for (int r = 0; r < 16; r++) {
                float4 xv = *(const float4*)&xs[r * 64 + kk];
                acc[r] += xv.x * w0 + xv.y * w1 + xv.z * w2 + xv.w * w3;
            }
        }
        __syncthreads();
    }
    float b = bias[f];
#pragma unroll
    for (int r = 0; r < 16; r++) {
        int row = row0 + r;
        if (row < nrows) {
            float v = acc[r] + b;
            out[row * 128 + f] = v;
            g_x0[row * 128 + f] = v;
        }
    }
}

// ---------------------------------------------------------------- APPNP step
// warp per row; lane handles 4 features (float4).  dir 0: g_h -> g_h2,
// dir 1: g_h2 -> g_h.  out = 0.9*agg + 0.1*x0
__global__ void k_appnp(int dir, int n) {
    int w = (blockIdx.x * blockDim.x + threadIdx.x) >> 5;
    int lane = threadIdx.x & 31;
    if (w >= n) return;
    const float4* __restrict__ h  = dir ? (const float4*)g_h2 : (const float4*)g_h;
    float4* __restrict__ out      = dir ? (float4*)g_h        : (float4*)g_h2;
    const float4* __restrict__ x0 = (const float4*)g_x0;

    int s = g_rowptr[w], e = g_rowptr[w + 1];
    float4 acc = make_float4(0.f, 0.f, 0.f, 0.f);
    int i = s;
    for (; i + 1 < e; i += 2) {
        int   c0 = g_col[i],  c1 = g_col[i + 1];
        float w0 = g_val[i],  w1 = g_val[i + 1];
        float4 a = h[c0 * 32 + lane];
        float4 b = h[c1 * 32 + lane];
        acc.x += w0 * a.x + w1 * b.x;
        acc.y += w0 * a.y + w1 * b.y;
        acc.z += w0 * a.z + w1 * b.z;
        acc.w += w0 * a.w + w1 * b.w;
    }
    if (i < e) {
        int c = g_col[i]; float wv = g_val[i];
        float4 a = h[c * 32 + lane];
        acc.x += wv * a.x; acc.y += wv * a.y; acc.z += wv * a.z; acc.w += wv * a.w;
    }
    float4 xv = x0[w * 32 + lane];
    float4 o;
    o.x = (1.f - ALPHA) * acc.x + ALPHA * xv.x;
    o.y = (1.f - ALPHA) * acc.y + ALPHA * xv.y;
    o.z = (1.f - ALPHA) * acc.z + ALPHA * xv.z;
    o.w = (1.f - ALPHA) * acc.w + ALPHA * xv.w;
    out[w * 32 + lane] = o;
}

// ---------------------------------------------------------------- link head
// warp per pair; reads relu(g_h2)
__global__ void k_link(const int* __restrict__ idx, const float* __restrict__ W3,
                       const float* __restrict__ b3, float* __restrict__ out, int p) {
    int w = (blockIdx.x * blockDim.x + threadIdx.x) >> 5;
    int lane = threadIdx.x & 31;
    if (w >= p) return;
    int i0 = idx[2 * w], i1 = idx[2 * w + 1];
    const float* a = g_h2 + (size_t)i0 * 128;
    const float* b = g_h2 + (size_t)i1 * 128;
    float l0 = 0.f, l1 = 0.f;
#pragma unroll
    for (int j = 0; j < 4; j++) {
        int k = lane + 32 * j;
        float av = fmaxf(a[k], 0.f);
        float bv = fmaxf(b[k], 0.f);
        l0 += av * W3[k]       + bv * W3[128 + k];
        l1 += av * W3[256 + k] + bv * W3[384 + k];
    }
#pragma unroll
    for (int off = 16; off; off >>= 1) {
        l0 += __shfl_down_sync(0xffffffffu, l0, off);
        l1 += __shfl_down_sync(0xffffffffu, l1, off);
    }
    if (lane == 0) {
        l0 += b3[0]; l1 += b3[1];
        float m = fmaxf(l0, l1);
        float lse = m + logf(expf(l0 - m) + expf(l1 - m));
        out[2 * w]     = l0 - lse;
        out[2 * w + 1] = l1 - lse;
    }
}

// ---------------------------------------------------------------- launch
extern "C" void kernel_launch(void* const* d_in, const int* in_sizes, int n_in,
                              void* d_out, int out_size) {
    const float* x   = (const float*)d_in[0];
    const int*   ei  = (const int*)  d_in[1];
    const int*   idx = (const int*)  d_in[2];
    const float* W1  = (const float*)d_in[3];
    const float* b1  = (const float*)d_in[4];
    const float* W2  = (const float*)d_in[5];
    const float* b2  = (const float*)d_in[6];
    const float* W3  = (const float*)d_in[7];
    const float* b3  = (const float*)d_in[8];
    float* out = (float*)d_out;

    int N = in_sizes[0] / D;
    int E = in_sizes[1] / 2;
    int P = in_sizes[2] / 2;
    const int* src = ei;
    const int* dst = ei + E;

    int nbScan = (N + 1023) / 1024;

    // --- CSR build ---
    k_init<<<(N + 255) / 256, 256>>>(N);
    k_hist<<<(E + 255) / 256, 256>>>(dst, E);
    k_scanA<<<nbScan, 1024>>>(N);
    k_scanB<<<1, 64>>>(nbScan);
    k_scanC<<<nbScan, 1024>>>(N);
    k_dinv<<<(N + 255) / 256, 256>>>(N);
    k_fill<<<(E + N + 255) / 256, 256>>>(src, dst, E, N);

    int gemmBlocks  = (N + 15) / 16;
    int appnpBlocks = (N * 32 + 255) / 256;

    // --- phase 1 ---
    k_gemm<<<gemmBlocks, 128>>>(x, W1, b1, /*mode=*/0, N);
    for (int k = 0; k < 10; k++)
        k_appnp<<<appnpBlocks, 256>>>(k & 1, N);       // ends in g_h

    // --- phase 2 ---
    k_gemm<<<gemmBlocks, 128>>>(nullptr, W2, b2, /*mode=*/1, N);  // g_h->g_h2
    for (int k = 0; k < 10; k++)
        k_appnp<<<appnpBlocks, 256>>>(1 - (k & 1), N); // ends in g_h2

    // --- link head ---
    k_link<<<(P * 32 + 255) / 256, 256>>>(idx, W3, b3, out, P);
}

// round 2
// speedup vs baseline: 1.2050x; 1.2050x over previous
#include <cuda_runtime.h>
#include <cuda_fp16.h>
#include <math.h>

// ---------------------------------------------------------------------------
// APPNP Link prediction.  N=50000, E=800000, P=200000, D=128, K=10 x 2, a=0.1
// Round 2: h/h2/x0 stored fp16 (fp32 accumulation) -> ~half the SpMM traffic.
//          (col,val) packed into 8B struct; 0.9 folded into CSR values.
// ---------------------------------------------------------------------------

#define D 128
#define NMAX 50176
#define EMAX 800000
#define CSRMAX (EMAX + NMAX)
#define ALPHA 0.1f

struct __align__(8) CV { int c; float v; };

__device__ __half g_h [NMAX * D];
__device__ __half g_h2[NMAX * D];
__device__ __half g_x0[NMAX * D];
__device__ int    g_deg[NMAX];
__device__ float  g_dinv[NMAX];
__device__ int    g_rowptr[NMAX + 1];
__device__ int    g_cursor[NMAX];
__device__ CV     g_cv[CSRMAX];
__device__ int    g_bsums[64];

// ---------------------------------------------------------------- CSR build
__global__ void k_init(int n) {
    int i = blockIdx.x * blockDim.x + threadIdx.x;
    if (i < n) { g_deg[i] = 1; g_cursor[i] = 0; }   // 1 = self loop
}

__global__ void k_hist(const int* __restrict__ dst, int e) {
    int i = blockIdx.x * blockDim.x + threadIdx.x;
    if (i < e) atomicAdd(&g_deg[dst[i]], 1);
}

__global__ void k_scanA(int n) {
    __shared__ int s[1024];
    int gid = blockIdx.x * 1024 + threadIdx.x;
    int v = (gid < n) ? g_deg[gid] : 0;
    s[threadIdx.x] = v;
    __syncthreads();
    for (int off = 1; off < 1024; off <<= 1) {
        int t = (threadIdx.x >= off) ? s[threadIdx.x - off] : 0;
        __syncthreads();
        s[threadIdx.x] += t;
        __syncthreads();
    }
    if (gid < n) g_rowptr[gid + 1] = s[threadIdx.x];
    if (threadIdx.x == 1023) g_bsums[blockIdx.x] = s[1023];
}

__global__ void k_scanB(int nb) {
    __shared__ int s[64];
    int v = (threadIdx.x < nb) ? g_bsums[threadIdx.x] : 0;
    s[threadIdx.x] = v;
    __syncthreads();
    for (int off = 1; off < 64; off <<= 1) {
        int t = (threadIdx.x >= off) ? s[threadIdx.x - off] : 0;
        __syncthreads();
        s[threadIdx.x] += t;
        __syncthreads();
    }
    if (threadIdx.x < nb) g_bsums[threadIdx.x] = s[threadIdx.x] - v;  // exclusive
}

__global__ void k_scanC(int n) {
    int gid = blockIdx.x * 1024 + threadIdx.x;
    if (gid < n) g_rowptr[gid + 1] += g_bsums[blockIdx.x];
    if (gid == 0) g_rowptr[0] = 0;
}

__global__ void k_dinv(int n) {
    int i = blockIdx.x * blockDim.x + threadIdx.x;
    if (i < n) g_dinv[i] = rsqrtf((float)g_deg[i]);
}

__global__ void k_fill(const int* __restrict__ src, const int* __restrict__ dst,
                       int e, int n) {
    int i = blockIdx.x * blockDim.x + threadIdx.x;
    if (i < e) {
        int s = src[i], d = dst[i];
        int pos = g_rowptr[d] + atomicAdd(&g_cursor[d], 1);
        CV cv; cv.c = s; cv.v = 0.9f * g_dinv[s] * g_dinv[d];   // fold (1-alpha)
        g_cv[pos] = cv;
    } else if (i < e + n) {
        int nd = i - e;
        int pos = g_rowptr[nd] + atomicAdd(&g_cursor[nd], 1);
        float dv = g_dinv[nd];
        CV cv; cv.c = nd; cv.v = 0.9f * dv * dv;
        g_cv[pos] = cv;
    }
}

// ---------------------------------------------------------------- dense GEMM
// out[row][f] = sum_k in[row][k] * W[f][k] + bias[f]   (fp32 math)
// mode 0: in = Xext fp32 (no relu), out -> g_h  and g_x0   (fp16)
// mode 1: in = g_h  fp16 (relu),    out -> g_h2 and g_x0   (fp16)
__global__ void k_gemm(const float* __restrict__ Xext, const float* __restrict__ W,
                       const float* __restrict__ bias, int mode, int nrows) {
    __shared__ float Wt[64 * 129];                 // Wt[kk][f], padded
    __shared__ __align__(16) float xs[16 * 64];    // xs[r][kk]
    __half* out = (mode == 0) ? g_h : g_h2;

    int f = threadIdx.x;           // 0..127, output column
    int row0 = blockIdx.x * 16;
    float acc[16];
#pragma unroll
    for (int r = 0; r < 16; r++) acc[r] = 0.f;

    for (int kc = 0; kc < 128; kc += 64) {
        for (int i = f; i < 64 * 128; i += 128) {
            int kk = i & 63, f2 = i >> 6;
            Wt[kk * 129 + f2] = W[f2 * 128 + kc + kk];
        }
        for (int i = f; i < 16 * 64; i += 128) {
            int r = i >> 6, kk = i & 63;
            int row = row0 + r;
            float v = 0.f;
            if (row < nrows) {
                if (mode) v = fmaxf(__half2float(g_h[row * 128 + kc + kk]), 0.f);
                else      v = Xext[row * 128 + kc + kk];
            }
            xs[i] = v;
        }
        __syncthreads();
#pragma unroll
        for (int kk = 0; kk < 64; kk += 4) {
            float w0 = Wt[(kk + 0) * 129 + f];
            float w1 = Wt[(kk + 1) * 129 + f];
            float w2 = Wt[(kk + 2) * 129 + f];
            float w3 = Wt[(kk + 3) * 129 + f];
#pragma unroll
            for (int r = 0; r < 16; r++) {
                float4 xv = *(const float4*)&xs[r * 64 + kk];
                acc[r] += xv.x * w0 + xv.y * w1 + xv.z * w2 + xv.w * w3;
            }
        }
        __syncthreads();
    }
    float b = bias[f];
#pragma unroll
    for (int r = 0; r < 16; r++) {
        int row = row0 + r;
        if (row < nrows) {
            __half v = __float2half(acc[r] + b);
            out [row * 128 + f] = v;
            g_x0[row * 128 + f] = v;
        }
    }
}

// ---------------------------------------------------------------- APPNP step
// warp per row; lane handles 4 fp16 features (8B load).
// dir 0: g_h -> g_h2,  dir 1: g_h2 -> g_h.   out = agg + 0.1*x0
// (0.9 already folded into CSR values)
__device__ __forceinline__ float4 h4load(const __half* base, int row, int lane) {
    uint2 raw = ((const uint2*)base)[row * 32 + lane];
    __half2 a = *(__half2*)&raw.x;
    __half2 b = *(__half2*)&raw.y;
    float2 fa = __half22float2(a);
    float2 fb = __half22float2(b);
    return make_float4(fa.x, fa.y, fb.x, fb.y);
}

__global__ void k_appnp(int dir, int n) {
    int w = (blockIdx.x * blockDim.x + threadIdx.x) >> 5;
    int lane = threadIdx.x & 31;
    if (w >= n) return;
    const __half* __restrict__ h = dir ? g_h2 : g_h;
    __half* __restrict__ out     = dir ? g_h  : g_h2;

    int s = g_rowptr[w], e = g_rowptr[w + 1];
    float4 acc = make_float4(0.f, 0.f, 0.f, 0.f);
    int i = s;
    for (; i + 1 < e; i += 2) {
        CV cv0 = g_cv[i];
        CV cv1 = g_cv[i + 1];
        float4 a = h4load(h, cv0.c, lane);
        float4 b = h4load(h, cv1.c, lane);
        acc.x += cv0.v * a.x + cv1.v * b.x;
        acc.y += cv0.v * a.y + cv1.v * b.y;
        acc.z += cv0.v * a.z + cv1.v * b.z;
        acc.w += cv0.v * a.w + cv1.v * b.w;
    }
    if (i < e) {
        CV cv = g_cv[i];
        float4 a = h4load(h, cv.c, lane);
        acc.x += cv.v * a.x; acc.y += cv.v * a.y;
        acc.z += cv.v * a.z; acc.w += cv.v * a.w;
    }
    float4 xv = h4load(g_x0, w, lane);
    __half2 o0 = __floats2half2_rn(acc.x + ALPHA * xv.x, acc.y + ALPHA * xv.y);
    __half2 o1 = __floats2half2_rn(acc.z + ALPHA * xv.z, acc.w + ALPHA * xv.w);
    uint2 raw;
    raw.x = *(unsigned*)&o0;
    raw.y = *(unsigned*)&o1;
    ((uint2*)out)[w * 32 + lane] = raw;
}

// ---------------------------------------------------------------- link head
// warp per pair; reads relu(g_h2) fp16
__global__ void k_link(const int* __restrict__ idx, const float* __restrict__ W3,
                       const float* __restrict__ b3, float* __restrict__ out, int p) {
    int w = (blockIdx.x * blockDim.x + threadIdx.x) >> 5;
    int lane = threadIdx.x & 31;
    if (w >= p) return;
    int i0 = idx[2 * w], i1 = idx[2 * w + 1];
    const __half* a = g_h2 + (size_t)i0 * 128;
    const __half* b = g_h2 + (size_t)i1 * 128;
    float l0 = 0.f, l1 = 0.f;
#pragma unroll
    for (int j = 0; j < 4; j++) {
        int k = lane + 32 * j;
        float av = fmaxf(__half2float(a[k]), 0.f);
        float bv = fmaxf(__half2float(b[k]), 0.f);
        l0 += av * W3[k]       + bv * W3[128 + k];
        l1 += av * W3[256 + k] + bv * W3[384 + k];
    }
#pragma unroll
    for (int off = 16; off; off >>= 1) {
        l0 += __shfl_down_sync(0xffffffffu, l0, off);
        l1 += __shfl_down_sync(0xffffffffu, l1, off);
    }
    if (lane == 0) {
        l0 += b3[0]; l1 += b3[1];
        float m = fmaxf(l0, l1);
        float lse = m + logf(expf(l0 - m) + expf(l1 - m));
        out[2 * w]     = l0 - lse;
        out[2 * w + 1] = l1 - lse;
    }
}

// ---------------------------------------------------------------- launch
extern "C" void kernel_launch(void* const* d_in, const int* in_sizes, int n_in,
                              void* d_out, int out_size) {
    const float* x   = (const float*)d_in[0];
    const int*   ei  = (const int*)  d_in[1];
    const int*   idx = (const int*)  d_in[2];
    const float* W1  = (const float*)d_in[3];
    const float* b1  = (const float*)d_in[4];
    const float* W2  = (const float*)d_in[5];
    const float* b2  = (const float*)d_in[6];
    const float* W3  = (const float*)d_in[7];
    const float* b3  = (const float*)d_in[8];
    float* out = (float*)d_out;

    int N = in_sizes[0] / D;
    int E = in_sizes[1] / 2;
    int P = in_sizes[2] / 2;
    const int* src = ei;
    const int* dst = ei + E;

    int nbScan = (N + 1023) / 1024;

    // --- CSR build ---
    k_init<<<(N + 255) / 256, 256>>>(N);
    k_hist<<<(E + 255) / 256, 256>>>(dst, E);
    k_scanA<<<nbScan, 1024>>>(N);
    k_scanB<<<1, 64>>>(nbScan);
    k_scanC<<<nbScan, 1024>>>(N);
    k_dinv<<<(N + 255) / 256, 256>>>(N);
    k_fill<<<(E + N + 255) / 256, 256>>>(src, dst, E, N);

    int gemmBlocks  = (N + 15) / 16;
    int appnpBlocks = (N * 32 + 255) / 256;

    // --- phase 1 ---
    k_gemm<<<gemmBlocks, 128>>>(x, W1, b1, /*mode=*/0, N);
    for (int k = 0; k < 10; k++)
        k_appnp<<<appnpBlocks, 256>>>(k & 1, N);       // ends in g_h

    // --- phase 2 ---
    k_gemm<<<gemmBlocks, 128>>>(nullptr, W2, b2, /*mode=*/1, N);  // g_h->g_h2
    for (int k = 0; k < 10; k++)
        k_appnp<<<appnpBlocks, 256>>>(1 - (k & 1), N); // ends in g_h2

    // --- link head ---
    k_link<<<(P * 32 + 255) / 256, 256>>>(idx, W3, b3, out, P);
}

// round 3
// speedup vs baseline: 1.3243x; 1.0990x over previous
#include <cuda_runtime.h>
#include <cuda_fp16.h>
#include <mma.h>
#include <math.h>

using namespace nvcuda;

// ---------------------------------------------------------------------------
// APPNP Link prediction.  N=50000, E=800000, P=200000, D=128, K=10 x 2, a=0.1
// Round 3: wmma tensor-core GEMMs (fp16 in, fp32 accum), half2 link head,
//          4x-unrolled SpMM.  h/h2/x0 fp16; (col,val) packed 8B; 0.9 folded.
// ---------------------------------------------------------------------------

#define D 128
#define NMAX 50176
#define EMAX 800000
#define CSRMAX (EMAX + NMAX)
#define ALPHA 0.1f

struct __align__(8) CV { int c; float v; };

__device__ __half g_h [NMAX * D];
__device__ __half g_h2[NMAX * D];
__device__ __half g_x0[NMAX * D];
__device__ __half g_Wh[D * D];
__device__ int    g_deg[NMAX];
__device__ float  g_dinv[NMAX];
__device__ int    g_rowptr[NMAX + 1];
__device__ int    g_cursor[NMAX];
__device__ CV     g_cv[CSRMAX];
__device__ int    g_bsums[64];

// ---------------------------------------------------------------- CSR build
__global__ void k_init(int n) {
    int i = blockIdx.x * blockDim.x + threadIdx.x;
    if (i < n) { g_deg[i] = 1; g_cursor[i] = 0; }   // 1 = self loop
}

__global__ void k_hist(const int* __restrict__ dst, int e) {
    int i = blockIdx.x * blockDim.x + threadIdx.x;
    if (i < e) atomicAdd(&g_deg[dst[i]], 1);
}

__global__ void k_scanA(int n) {
    __shared__ int s[1024];
    int gid = blockIdx.x * 1024 + threadIdx.x;
    int v = (gid < n) ? g_deg[gid] : 0;
    s[threadIdx.x] = v;
    __syncthreads();
    for (int off = 1; off < 1024; off <<= 1) {
        int t = (threadIdx.x >= off) ? s[threadIdx.x - off] : 0;
        __syncthreads();
        s[threadIdx.x] += t;
        __syncthreads();
    }
    if (gid < n) g_rowptr[gid + 1] = s[threadIdx.x];
    if (threadIdx.x == 1023) g_bsums[blockIdx.x] = s[1023];
}

__global__ void k_scanB(int nb) {
    __shared__ int s[64];
    int v = (threadIdx.x < nb) ? g_bsums[threadIdx.x] : 0;
    s[threadIdx.x] = v;
    __syncthreads();
    for (int off = 1; off < 64; off <<= 1) {
        int t = (threadIdx.x >= off) ? s[threadIdx.x - off] : 0;
        __syncthreads();
        s[threadIdx.x] += t;
        __syncthreads();
    }
    if (threadIdx.x < nb) g_bsums[threadIdx.x] = s[threadIdx.x] - v;  // exclusive
}

__global__ void k_scanC(int n) {
    int gid = blockIdx.x * 1024 + threadIdx.x;
    if (gid < n) g_rowptr[gid + 1] += g_bsums[blockIdx.x];
    if (gid == 0) g_rowptr[0] = 0;
}

__global__ void k_dinv(int n) {
    int i = blockIdx.x * blockDim.x + threadIdx.x;
    if (i < n) g_dinv[i] = rsqrtf((float)g_deg[i]);
}

__global__ void k_fill(const int* __restrict__ src, const int* __restrict__ dst,
                       int e, int n) {
    int i = blockIdx.x * blockDim.x + threadIdx.x;
    if (i < e) {
        int s = src[i], d = dst[i];
        int pos = g_rowptr[d] + atomicAdd(&g_cursor[d], 1);
        CV cv; cv.c = s; cv.v = 0.9f * g_dinv[s] * g_dinv[d];   // fold (1-alpha)
        g_cv[pos] = cv;
    } else if (i < e + n) {
        int nd = i - e;
        int pos = g_rowptr[nd] + atomicAdd(&g_cursor[nd], 1);
        float dv = g_dinv[nd];
        CV cv; cv.c = nd; cv.v = 0.9f * dv * dv;
        g_cv[pos] = cv;
    }
}

// ---------------------------------------------------------------- GEMM (wmma)
__global__ void k_convW(const float* __restrict__ W) {
    int i = blockIdx.x * blockDim.x + threadIdx.x;
    if (i < D * D) g_Wh[i] = __float2half(W[i]);
}

// out[row][f] = sum_k in[row][k] * W[f][k] + bias[f]   (tensor core, fp32 acc)
// mode 0: in = Xext fp32 (no relu), out -> g_h  and g_x0
// mode 1: in = g_h  fp16 (relu),    out -> g_h2 and g_x0
// Block: 256 thr (8 warps), tile 32 rows x 128 cols.
// Warp w: mi = w>>2 (m-tile of 16), nj = w&3 (n-tile of 32 = 2 wmma frags).
__global__ void k_gemm(const float* __restrict__ Xext, const float* __restrict__ bias,
                       int mode, int nrows) {
    __shared__ __align__(32) char sbuf[16384];
    __half* Xs = (__half*)sbuf;          // [32][128] fp16  (8KB)
    float*  Cs = (float*)sbuf;           // [32][128] fp32  (16KB, reused after sync)

    int tid = threadIdx.x;
    int row0 = blockIdx.x * 32;

    for (int i = tid; i < 32 * 128; i += 256) {
        int r = i >> 7, k = i & 127;
        int row = row0 + r;
        float v = 0.f;
        if (row < nrows) {
            if (mode) v = fmaxf(__half2float(g_h[row * 128 + k]), 0.f);
            else      v = Xext[row * 128 + k];
        }
        Xs[i] = __float2half(v);
    }
    __syncthreads();

    int w  = tid >> 5;
    int mi = w >> 2;          // 0..1
    int nj = w & 3;           // 0..3

    wmma::fragment<wmma::accumulator, 16, 16, 16, float> c0, c1;
    wmma::fill_fragment(c0, 0.f);
    wmma::fill_fragment(c1, 0.f);

#pragma unroll
    for (int k = 0; k < 128; k += 16) {
        wmma::fragment<wmma::matrix_a, 16, 16, 16, __half, wmma::row_major> a;
        wmma::load_matrix_sync(a, Xs + mi * 16 * 128 + k, 128);
        wmma::fragment<wmma::matrix_b, 16, 16, 16, __half, wmma::col_major> b0, b1;
        // B(k,n) = W[n][k]; col_major over g_Wh with ldb=128
        wmma::load_matrix_sync(b0, g_Wh + (nj * 32)      * 128 + k, 128);
        wmma::load_matrix_sync(b1, g_Wh + (nj * 32 + 16) * 128 + k, 128);
        wmma::mma_sync(c0, a, b0, c0);
        wmma::mma_sync(c1, a, b1, c1);
    }
    __syncthreads();   // all warps done reading Xs
    wmma::store_matrix_sync(Cs + mi * 16 * 128 + nj * 32,      c0, 128, wmma::mem_row_major);
    wmma::store_matrix_sync(Cs + mi * 16 * 128 + nj * 32 + 16, c1, 128, wmma::mem_row_major);
    __syncthreads();

    __half* out = mode ? g_h2 : g_h;
    for (int i = tid; i < 32 * 128; i += 256) {
        int r = i >> 7, f = i & 127;
        int row = row0 + r;
        if (row < nrows) {
            __half v = __float2half(Cs[i] + bias[f]);
            out [row * 128 + f] = v;
            g_x0[row * 128 + f] = v;
        }
    }
}

// ---------------------------------------------------------------- APPNP step
__device__ __forceinline__ float4 h4load(const __half* base, int row, int lane) {
    uint2 raw = ((const uint2*)base)[row * 32 + lane];
    __half2 a = *(__half2*)&raw.x;
    __half2 b = *(__half2*)&raw.y;
    float2 fa = __half22float2(a);
    float2 fb = __half22float2(b);
    return make_float4(fa.x, fa.y, fb.x, fb.y);
}

// warp per row; lane handles 4 fp16 features.  dir 0: g_h->g_h2, dir 1: back.
// out = agg + 0.1*x0  (0.9 folded into CSR values)
__global__ void k_appnp(int dir, int n) {
    int w = (blockIdx.x * blockDim.x + threadIdx.x) >> 5;
    int lane = threadIdx.x & 31;
    if (w >= n) return;
    const __half* __restrict__ h = dir ? g_h2 : g_h;
    __half* __restrict__ out     = dir ? g_h  : g_h2;

    int s = g_rowptr[w], e = g_rowptr[w + 1];
    float4 acc = make_float4(0.f, 0.f, 0.f, 0.f);
    int i = s;
    for (; i + 3 < e; i += 4) {
        CV cv0 = g_cv[i];
        CV cv1 = g_cv[i + 1];
        CV cv2 = g_cv[i + 2];
        CV cv3 = g_cv[i + 3];
        float4 a = h4load(h, cv0.c, lane);
        float4 b = h4load(h, cv1.c, lane);
        float4 c = h4load(h, cv2.c, lane);
        float4 d = h4load(h, cv3.c, lane);
        acc.x += cv0.v * a.x + cv1.v * b.x + cv2.v * c.x + cv3.v * d.x;
        acc.y += cv0.v * a.y + cv1.v * b.y + cv2.v * c.y + cv3.v * d.y;
        acc.z += cv0.v * a.z + cv1.v * b.z + cv2.v * c.z + cv3.v * d.z;
        acc.w += cv0.v * a.w + cv1.v * b.w + cv2.v * c.w + cv3.v * d.w;
    }
    for (; i < e; i++) {
        CV cv = g_cv[i];
        float4 a = h4load(h, cv.c, lane);
        acc.x += cv.v * a.x; acc.y += cv.v * a.y;
        acc.z += cv.v * a.z; acc.w += cv.v * a.w;
    }
    float4 xv = h4load(g_x0, w, lane);
    __half2 o0 = __floats2half2_rn(acc.x + ALPHA * xv.x, acc.y + ALPHA * xv.y);
    __half2 o1 = __floats2half2_rn(acc.z + ALPHA * xv.z, acc.w + ALPHA * xv.w);
    uint2 raw;
    raw.x = *(unsigned*)&o0;
    raw.y = *(unsigned*)&o1;
    ((uint2*)out)[w * 32 + lane] = raw;
}

// ---------------------------------------------------------------- link head
// warp per pair; half2 loads of relu(g_h2)
__global__ void k_link(const int* __restrict__ idx, const float* __restrict__ W3,
                       const float* __restrict__ b3, float* __restrict__ out, int p) {
    int w = (blockIdx.x * blockDim.x + threadIdx.x) >> 5;
    int lane = threadIdx.x & 31;
    if (w >= p) return;
    int i0 = idx[2 * w], i1 = idx[2 * w + 1];
    const __half2* a2 = (const __half2*)(g_h2 + (size_t)i0 * 128);
    const __half2* b2 = (const __half2*)(g_h2 + (size_t)i1 * 128);
    float l0 = 0.f, l1 = 0.f;
#pragma unroll
    for (int j = 0; j < 2; j++) {
        int k2 = lane + 32 * j;          // half2 index 0..63
        float2 af = __half22float2(a2[k2]);
        float2 bf = __half22float2(b2[k2]);
        af.x = fmaxf(af.x, 0.f); af.y = fmaxf(af.y, 0.f);
        bf.x = fmaxf(bf.x, 0.f); bf.y = fmaxf(bf.y, 0.f);
        int k = 2 * k2;
        l0 += af.x * W3[k]       + af.y * W3[k + 1]
            + bf.x * W3[128 + k] + bf.y * W3[128 + k + 1];
        l1 += af.x * W3[256 + k] + af.y * W3[256 + k + 1]
            + bf.x * W3[384 + k] + bf.y * W3[384 + k + 1];
    }
#pragma unroll
    for (int off = 16; off; off >>= 1) {
        l0 += __shfl_down_sync(0xffffffffu, l0, off);
        l1 += __shfl_down_sync(0xffffffffu, l1, off);
    }
    if (lane == 0) {
        l0 += b3[0]; l1 += b3[1];
        float m = fmaxf(l0, l1);
        float lse = m + logf(expf(l0 - m) + expf(l1 - m));
        out[2 * w]     = l0 - lse;
        out[2 * w + 1] = l1 - lse;
    }
}

// ---------------------------------------------------------------- launch
extern "C" void kernel_launch(void* const* d_in, const int* in_sizes, int n_in,
                              void* d_out, int out_size) {
    const float* x   = (const float*)d_in[0];
    const int*   ei  = (const int*)  d_in[1];
    const int*   idx = (const int*)  d_in[2];
    const float* W1  = (const float*)d_in[3];
    const float* b1  = (const float*)d_in[4];
    const float* W2  = (const float*)d_in[5];
    const float* b2  = (const float*)d_in[6];
    const float* W3  = (const float*)d_in[7];
    const float* b3  = (const float*)d_in[8];
    float* out = (float*)d_out;

    int N = in_sizes[0] / D;
    int E = in_sizes[1] / 2;
    int P = in_sizes[2] / 2;
    const int* src = ei;
    const int* dst = ei + E;

    int nbScan = (N + 1023) / 1024;

    // --- CSR build ---
    k_init<<<(N + 255) / 256, 256>>>(N);
    k_hist<<<(E + 255) / 256, 256>>>(dst, E);
    k_scanA<<<nbScan, 1024>>>(N);
    k_scanB<<<1, 64>>>(nbScan);
    k_scanC<<<nbScan, 1024>>>(N);
    k_dinv<<<(N + 255) / 256, 256>>>(N);
    k_fill<<<(E + N + 255) / 256, 256>>>(src, dst, E, N);

    int gemmBlocks  = (N + 31) / 32;
    int appnpBlocks = (N * 32 + 255) / 256;

    // --- phase 1 ---
    k_convW<<<(D * D + 255) / 256, 256>>>(W1);
    k_gemm<<<gemmBlocks, 256>>>(x, b1, /*mode=*/0, N);
    for (int k = 0; k < 10; k++)
        k_appnp<<<appnpBlocks, 256>>>(k & 1, N);       // ends in g_h

    // --- phase 2 ---
    k_convW<<<(D * D + 255) / 256, 256>>>(W2);
    k_gemm<<<gemmBlocks, 256>>>(nullptr, b2, /*mode=*/1, N);  // g_h->g_h2
    for (int k = 0; k < 10; k++)
        k_appnp<<<appnpBlocks, 256>>>(1 - (k & 1), N); // ends in g_h2

    // --- link head ---
    k_link<<<(P * 32 + 255) / 256, 256>>>(idx, W3, b3, out, P);
}